// round 12
// baseline (speedup 1.0000x reference)
#include <cuda_runtime.h>
#include <cuda_bf16.h>
#include <math.h>
#include <stdint.h>

#define BSZ 256        // batch B
#define NSEQ 4096      // K*B
#define H 64
#define G4 256
#define ZXD 320
#define LSTM_IN 322
#define TT 50
#define SEQB 16        // seqs per recurrent block (2 CTAs/SM)

__device__ __forceinline__ float tanhg(float x) {
    float y;
    asm("tanh.approx.f32 %0, %1;" : "=f"(y) : "f"(x));
    return y;
}
__device__ __forceinline__ float sigg(float x) {
    return fmaf(0.5f, tanhg(0.5f * x), 0.5f);
}
__device__ __forceinline__ uint32_t f2tf(float x) {
    uint32_t r;
    asm("cvt.rna.tf32.f32 %0, %1;" : "=r"(r) : "f"(x));
    return r;
}

// m16n8k8 tf32 mma, D += A*B
__device__ __forceinline__ void mma8(float* d, const uint4& a,
                                     uint32_t b0, uint32_t b1) {
    asm volatile(
        "mma.sync.aligned.m16n8k8.row.col.f32.tf32.tf32.f32 "
        "{%0,%1,%2,%3}, {%4,%5,%6,%7}, {%8,%9}, {%0,%1,%2,%3};"
        : "+f"(d[0]), "+f"(d[1]), "+f"(d[2]), "+f"(d[3])
        : "r"(a.x), "r"(a.y), "r"(a.z), "r"(a.w), "r"(b0), "r"(b1));
}
// m16n8k16 bf16 mma, D += A*B
__device__ __forceinline__ void mma16(float* d, const uint4& a,
                                      uint32_t b0, uint32_t b1) {
    asm volatile(
        "mma.sync.aligned.m16n8k16.row.col.f32.bf16.bf16.f32 "
        "{%0,%1,%2,%3}, {%4,%5,%6,%7}, {%8,%9}, {%0,%1,%2,%3};"
        : "+f"(d[0]), "+f"(d[1]), "+f"(d[2]), "+f"(d[3])
        : "r"(a.x), "r"(a.y), "r"(a.z), "r"(a.w), "r"(b0), "r"(b1));
}

// scratch
__device__ float g_G0[NSEQ * G4];        // [n][u*4 + q]
__device__ float g_h0[NSEQ * H];
__device__ float g_c0[NSEQ * H];
__device__ float g_hs[NSEQ * TT * H];    // full h history (52 MB)

// ---------------------------------------------------------------------------
// Phase 1 (unchanged):  [G0 | h0 | c0] = zx @ [Wih[:, :320] | Wh0 | Wc0]^T
// ---------------------------------------------------------------------------
__global__ __launch_bounds__(256) void phase1_kernel(
    const float* __restrict__ x, const float* __restrict__ z,
    const float* __restrict__ Wih, const float* __restrict__ Wh0,
    const float* __restrict__ Wc0,
    const float* __restrict__ bih, const float* __restrict__ bhh,
    const float* __restrict__ bh0, const float* __restrict__ bc0)
{
    __shared__ float As[16][68];
    __shared__ float Ws[16][68];
    const int tid = threadIdx.x;
    const int n0 = blockIdx.x * 64;
    const int c0 = blockIdx.y * 64;
    const int tx = tid & 15, ty = tid >> 4;
    float acc[4][4] = {};

    for (int kt = 0; kt < ZXD; kt += 16) {
        #pragma unroll
        for (int i = 0; i < 4; i++) {
            int e = tid + i * 256;
            int kk = e & 15, rr = e >> 4;
            int n = n0 + rr, m = kt + kk;
            float v = (m < H) ? z[n * H + m]
                              : x[(n & (BSZ - 1)) * 256 + (m - H)];
            As[kk][rr] = v;
        }
        #pragma unroll
        for (int i = 0; i < 4; i++) {
            int e = tid + i * 256;
            int kk = e & 15, cc = e >> 4;
            int j = c0 + cc, m = kt + kk;
            float v;
            if (j < G4)          v = Wih[j * LSTM_IN + m];
            else if (j < G4 + H) v = Wh0[(j - G4) * ZXD + m];
            else                 v = Wc0[(j - G4 - H) * ZXD + m];
            Ws[kk][cc] = v;
        }
        __syncthreads();
        #pragma unroll
        for (int kk = 0; kk < 16; kk++) {
            float a[4], b[4];
            #pragma unroll
            for (int i = 0; i < 4; i++) a[i] = As[kk][ty * 4 + i];
            #pragma unroll
            for (int j = 0; j < 4; j++) b[j] = Ws[kk][tx * 4 + j];
            #pragma unroll
            for (int i = 0; i < 4; i++)
                #pragma unroll
                for (int j = 0; j < 4; j++)
                    acc[i][j] += a[i] * b[j];
        }
        __syncthreads();
    }

    #pragma unroll
    for (int i = 0; i < 4; i++) {
        int n = n0 + ty * 4 + i;
        #pragma unroll
        for (int j = 0; j < 4; j++) {
            int col = c0 + tx * 4 + j;
            float v = acc[i][j];
            if (col < G4) {
                int u = col & 63, q = col >> 6;
                g_G0[n * G4 + u * 4 + q] = v + bih[col] + bhh[col];
            }
            else if (col < G4 + H) g_h0[n * H + (col - G4)]     = v + bh0[col - G4];
            else                   g_c0[n * H + (col - G4 - H)] = v + bc0[col - G4 - H];
        }
    }
}

// ---------------------------------------------------------------------------
// Phase 2: minimal sequential core.  256 blocks x 16 seqs x 256 threads,
// 2 CTAs/SM.  Per step: bf16 3-term gates MMA (60 HMMA/warp) -> pointwise
// -> h store (smem bf16 frags + fp32 g_hs).  2 barriers/step.
// A[16 x 80]: cols 0-63 h, 64 dx, 65 dy, rest 0.  B gates [256 x 80],
// hi+lo bf16 packed per-lane as uint4 [bh0,bh1,bl0,bl1].
// ---------------------------------------------------------------------------
#define SM2_BG  0                       // 32nt*5kt*32 lanes * uint4 = 20480 w
#define SM2_AH  20480                   // 5kt*32*4 = 640 w
#define SM2_AL  21120                   // 640 w
#define SM2_TOT 21760
#define SMEM2 (SM2_TOT * 4)

__global__ __launch_bounds__(256, 2) void phase2_kernel(
    const float* __restrict__ inp_seqs, const float* __restrict__ pred_seqs,
    const float* __restrict__ Whh, const float* __restrict__ Wih)
{
    extern __shared__ float sm[];
    uint32_t* smu = (uint32_t*)sm;
    const int tid  = threadIdx.x;
    const int lane = tid & 31;
    const int warp = tid >> 5;        // 0..7
    const int m4   = lane & 3;
    const int sr   = lane >> 2;       // 0..7
    const int nb   = blockIdx.x * SEQB;

    // ---- zero A regions (covers k>=66 pads) ----
    for (int e = tid; e < 1280; e += 256) sm[SM2_AH + e] = 0.f;

    // ---- stage B gates: bf16 hi+lo, fragment-major, permuted cols ----
    for (int e = tid; e < 256 * 80; e += 256) {
        int j = e / 80, k = e - (e / 80) * 80;
        int w = j >> 5, i = (j >> 3) & 3, m = (j >> 1) & 3, b = j & 1;
        int u = 8 * w + 2 * m + (i >> 1);
        int q = 2 * (i & 1) + b;
        int row = q * 64 + u;
        float v = 0.f;
        if (k < 64)       v = Whh[row * 64 + k];
        else if (k == 64) v = Wih[row * LSTM_IN + 320];
        else if (k == 65) v = Wih[row * LSTM_IN + 321];
        __nv_bfloat16 hb = __float2bfloat16(v);
        __nv_bfloat16 lb = __float2bfloat16(v - __bfloat162float(hb));
        int nt = j >> 3, kt = k >> 4, kk = k & 15;
        int lanep = (j & 7) * 4 + ((kk >> 1) & 3);
        int breg = kk >> 3, half = kk & 1;
        char* p = (char*)sm + (SM2_BG + ((nt * 5 + kt) * 32 + lanep) * 4) * 4
                  + breg * 4 + half * 2;
        *(__nv_bfloat16*)p       = hb;   // hi at bytes [0,8)
        *(__nv_bfloat16*)(p + 8) = lb;   // lo at bytes [8,16)
    }
    __syncthreads();   // zeros done before h0/d0 partial fills

    // ---- stage A: h0 (bf16 hi+lo) ----
    for (int e = tid; e < SEQB * 64; e += 256) {
        int s = e >> 6, k = e & 63;
        float v = g_h0[(nb + s) * 64 + k];
        __nv_bfloat16 hb = __float2bfloat16(v);
        __nv_bfloat16 lb = __float2bfloat16(v - __bfloat162float(hb));
        int kt = k >> 4, kk = k & 15;
        int lanep = (s & 7) * 4 + ((kk >> 1) & 3);
        int reg = (s >> 3) + 2 * (kk >> 3), half = kk & 1;
        int byteoff = ((kt * 32 + lanep) * 4 + reg) * 4 + half * 2;
        *(__nv_bfloat16*)((char*)(sm + SM2_AH) + byteoff) = hb;
        *(__nv_bfloat16*)((char*)(sm + SM2_AL) + byteoff) = lb;
    }
    // ---- stage A: d0 = tgt_present ----
    if (tid < SEQB) {
        int s = tid;
        int b = (nb + s) & (BSZ - 1);
        float dx = inp_seqs[(b * 8 + 7) * 24 + 20];
        float dy = inp_seqs[(b * 8 + 7) * 24 + 21];
        __nv_bfloat16 hx = __float2bfloat16(dx), hy = __float2bfloat16(dy);
        float rx = dx - __bfloat162float(hx), ry = dy - __bfloat162float(hy);
        __nv_bfloat16 lx = __float2bfloat16(rx), ly = __float2bfloat16(ry);
        int widx = (4 * 32 + (s & 7) * 4) * 4 + (s >> 3);
        smu[SM2_AH + widx] = (uint32_t)__bfloat16_as_ushort(hx)
                           | ((uint32_t)__bfloat16_as_ushort(hy) << 16);
        smu[SM2_AL + widx] = (uint32_t)__bfloat16_as_ushort(lx)
                           | ((uint32_t)__bfloat16_as_ushort(ly) << 16);
    }

    // ---- register state: 2 seqs x 2 units ----
    const int u0 = 8 * warp + 2 * m4;
    float G0r[2][2][4];
    float c[2][2];
    #pragma unroll
    for (int sq = 0; sq < 2; sq++) {
        int n = nb + sr + 8 * sq;
        #pragma unroll
        for (int dl = 0; dl < 2; dl++) {
            float4 g0 = *(const float4*)(g_G0 + n * 256 + (u0 + dl) * 4);
            G0r[sq][dl][0] = g0.x; G0r[sq][dl][1] = g0.y;
            G0r[sq][dl][2] = g0.z; G0r[sq][dl][3] = g0.w;
            c[sq][dl] = g_c0[n * 64 + u0 + dl];
        }
    }
    __syncthreads();

    for (int t = 1; t <= TT; t++) {
        // prefetch decode row for step t+1 (pred row t-1)
        float pdx = 0.f, pdy = 0.f;
        if (tid < SEQB && t < TT) {
            int b = (nb + tid) & (BSZ - 1);
            const float* pr = pred_seqs + (b * TT + (t - 1)) * 24 + 20;
            pdx = pr[0]; pdy = pr[1];
        }

        // ---- gates MMA: bf16 3-term, 60 HMMA ----
        float acc[4][4] = {};
        #pragma unroll
        for (int kt = 0; kt < 5; kt++) {
            uint4 ah = *(const uint4*)(smu + SM2_AH + (kt * 32 + lane) * 4);
            uint4 al = *(const uint4*)(smu + SM2_AL + (kt * 32 + lane) * 4);
            #pragma unroll
            for (int i = 0; i < 4; i++) {
                uint4 B = *(const uint4*)(smu + SM2_BG
                            + (((4 * warp + i) * 5 + kt) * 32 + lane) * 4);
                mma16(acc[i], ah, B.x, B.y);
                mma16(acc[i], al, B.x, B.y);
                mma16(acc[i], ah, B.z, B.w);
            }
        }

        // ---- pointwise LSTM ----
        float hreg[2][2];
        #pragma unroll
        for (int sq = 0; sq < 2; sq++) {
            #pragma unroll
            for (int dl = 0; dl < 2; dl++) {
                float gi = acc[2 * dl + 0][2 * sq + 0] + G0r[sq][dl][0];
                float gf = acc[2 * dl + 0][2 * sq + 1] + G0r[sq][dl][1];
                float gg = acc[2 * dl + 1][2 * sq + 0] + G0r[sq][dl][2];
                float go = acc[2 * dl + 1][2 * sq + 1] + G0r[sq][dl][3];
                float cc = sigg(gf) * c[sq][dl] + sigg(gi) * tanhg(gg);
                c[sq][dl] = cc;
                hreg[sq][dl] = sigg(go) * tanhg(cc);
            }
        }
        __syncthreads();   // all A reads done

        // ---- write h: smem bf16 frags (hi+lo) + fp32 history ----
        #pragma unroll
        for (int sq = 0; sq < 2; sq++) {
            float h0v = hreg[sq][0], h1v = hreg[sq][1];
            __nv_bfloat16 b0 = __float2bfloat16(h0v);
            __nv_bfloat16 b1 = __float2bfloat16(h1v);
            float r0 = h0v - __bfloat162float(b0);
            float r1 = h1v - __bfloat162float(b1);
            __nv_bfloat16 l0 = __float2bfloat16(r0);
            __nv_bfloat16 l1 = __float2bfloat16(r1);
            int widx = ((warp >> 1) * 32 + lane) * 4 + sq + 2 * (warp & 1);
            smu[SM2_AH + widx] = (uint32_t)__bfloat16_as_ushort(b0)
                               | ((uint32_t)__bfloat16_as_ushort(b1) << 16);
            smu[SM2_AL + widx] = (uint32_t)__bfloat16_as_ushort(l0)
                               | ((uint32_t)__bfloat16_as_ushort(l1) << 16);
            int s = sr + 8 * sq;
            *(float2*)(g_hs + (size_t)((nb + s) * TT + (t - 1)) * 64 + u0) =
                make_float2(h0v, h1v);
        }
        if (tid < SEQB && t < TT) {
            int s = tid;
            __nv_bfloat16 hx = __float2bfloat16(pdx), hy = __float2bfloat16(pdy);
            float rx = pdx - __bfloat162float(hx), ry = pdy - __bfloat162float(hy);
            __nv_bfloat16 lx = __float2bfloat16(rx), ly = __float2bfloat16(ry);
            int widx = (4 * 32 + (s & 7) * 4) * 4 + (s >> 3);
            smu[SM2_AH + widx] = (uint32_t)__bfloat16_as_ushort(hx)
                               | ((uint32_t)__bfloat16_as_ushort(hy) << 16);
            smu[SM2_AL + widx] = (uint32_t)__bfloat16_as_ushort(lx)
                               | ((uint32_t)__bfloat16_as_ushort(ly) << 16);
        }
        __syncthreads();   // new A visible
    }
}

// ---------------------------------------------------------------------------
// Phase 3: heads GEMM (tf32, single-term — proven) + GMM + LSE + sum over t.
// 2048 blocks x 2 seqs x 50 steps.  Rows: row = sl*64 + t (pad t>=50).
// warp = m-tile (8 x 16 rows = 128).  One thread per (seq,t) row for LSE.
// ---------------------------------------------------------------------------
#define SM3_BH  0                        // 12nt*9kt*32*2 = 6912 w
#define SM3_A   6912                     // 9kt*8mt*32*4 = 9216 w
#define SM3_PO  16128                    // 128*100 = 12800 w
#define SM3_LP  28928                    // 128 w
#define SM3_TOT 29056
#define SMEM3 (SM3_TOT * 4)

__global__ __launch_bounds__(256, 1) void phase3_kernel(
    const float* __restrict__ pred_seqs,
    const float* __restrict__ Wpi, const float* __restrict__ bpi,
    const float* __restrict__ Wmu, const float* __restrict__ bmu,
    const float* __restrict__ Wls, const float* __restrict__ bls,
    const float* __restrict__ Wcorr, const float* __restrict__ bcorr,
    float* __restrict__ out)
{
    extern __shared__ float sm[];
    uint32_t* smu = (uint32_t*)sm;
    const int tid  = threadIdx.x;
    const int lane = tid & 31;
    const int warp = tid >> 5;
    const int nb2  = blockIdx.x * 2;

    // ---- stage B heads (tf32, bias folded at k=64 via A's const-1 col) ----
    for (int e = tid; e < 96 * 72; e += 256) {
        int jj = e / 72, k = e - (e / 72) * 72;
        float v = 0.f;
        if (k < 64) {
            if (jj < 16)      v = Wpi[jj * 64 + k];
            else if (jj < 48) v = Wmu[(jj - 16) * 64 + k];
            else if (jj < 80) v = Wls[(jj - 48) * 64 + k];
            else              v = Wcorr[(jj - 80) * 64 + k];
        } else if (k == 64) {
            if (jj < 16)      v = bpi[jj];
            else if (jj < 48) v = bmu[jj - 16];
            else if (jj < 80) v = bls[jj - 48];
            else              v = bcorr[jj - 80];
        }
        int nt = jj >> 3, kt = k >> 3, kl = k & 7;
        int lanep = (jj & 7) * 4 + (kl & 3), r = kl >> 2;
        smu[SM3_BH + ((nt * 9 + kt) * 32 + lanep) * 2 + r] = f2tf(v);
    }
    // ---- stage A: h rows + const-1 col ----
    for (int e = tid; e < 128 * 72; e += 256) {
        int row = e / 72, k = e - (e / 72) * 72;
        int sl = row >> 6, tt2 = row & 63;
        float v;
        if (k < 64)
            v = (tt2 < TT) ? g_hs[(size_t)((nb2 + sl) * TT + tt2) * 64 + k] : 0.f;
        else
            v = (k == 64) ? 1.f : 0.f;
        int kt = k >> 3, kl = k & 7, mt = row >> 4, rr = row & 15;
        int lanep = (rr & 7) * 4 + (kl & 3);
        int reg = (rr >> 3) + 2 * (kl >> 2);
        smu[SM3_A + ((kt * 8 + mt) * 32 + lanep) * 4 + reg] = f2tf(v);
    }
    __syncthreads();

    // ---- heads mma: warp = m-tile, 12 n-tiles x 9 k-tiles ----
    float acc[12][4] = {};
    #pragma unroll
    for (int kt = 0; kt < 9; kt++) {
        uint4 a = *(const uint4*)(smu + SM3_A + ((kt * 8 + warp) * 32 + lane) * 4);
        #pragma unroll
        for (int nt = 0; nt < 12; nt++) {
            uint2 b = *(const uint2*)(smu + SM3_BH + ((nt * 9 + kt) * 32 + lane) * 2);
            mma8(acc[nt], a, b.x, b.y);
        }
    }
    {
        int row0 = 16 * warp + (lane >> 2);
        #pragma unroll
        for (int nt = 0; nt < 12; nt++) {
            int jc = 8 * nt + 2 * (lane & 3);
            *(float2*)(sm + SM3_PO + row0 * 100 + jc) =
                make_float2(acc[nt][0], acc[nt][1]);
            *(float2*)(sm + SM3_PO + (row0 + 8) * 100 + jc) =
                make_float2(acc[nt][2], acc[nt][3]);
        }
    }
    __syncthreads();

    // ---- GMM + LSE: one thread per (seq,t) row ----
    if (tid < 2 * TT) {
        int sl = tid / TT, tt2 = tid - sl * TT;
        int row = sl * 64 + tt2;
        int b = (nb2 + sl) & (BSZ - 1);
        const float* tg = pred_seqs + (b * TT + tt2) * 24 + 20;
        float txv = tg[0], tyv = tg[1];
        const float* pr = sm + SM3_PO + row * 100;
        float ac[16];
        float m1 = -1e30f, m2 = -1e30f;
        #pragma unroll
        for (int cc2 = 0; cc2 < 16; cc2++) {
            float pi  = pr[cc2];
            float mu0 = pr[16 + 2 * cc2], mu1 = pr[17 + 2 * cc2];
            float ls0 = fminf(fmaxf(pr[48 + 2 * cc2], -10.f), 10.f);
            float ls1 = fminf(fmaxf(pr[49 + 2 * cc2], -10.f), 10.f);
            float corr = tanhg(pr[80 + cc2]);
            float dx = txv - mu0, dy = tyv - mu1;
            float z0 = dx * __expf(-ls0);
            float z1 = dy * __expf(-ls1);
            float omr  = 1.f - corr * corr;
            float quad = z0 * z0 + z1 * z1 - 2.f * corr * z0 * z1;
            float cv = -1.8378770664093453f - (ls0 + ls1)
                       - 0.5f * __logf(omr) - 0.5f * __fdividef(quad, omr);
            float a = pi + cv;
            ac[cc2] = a;
            m1 = fmaxf(m1, a);
            m2 = fmaxf(m2, pi);
        }
        float s1 = 0.f, s2 = 0.f;
        #pragma unroll
        for (int cc2 = 0; cc2 < 16; cc2++) {
            s1 += __expf(ac[cc2] - m1);
            s2 += __expf(pr[cc2] - m2);
        }
        float lp = (m1 + __logf(s1)) - (m2 + __logf(s2));
        sm[SM3_LP + tid] = fminf(lp, 50.f);
    }
    __syncthreads();

    if (tid < 2) {
        float s = 0.f;
        #pragma unroll 10
        for (int i = 0; i < TT; i++) s += sm[SM3_LP + tid * TT + i];
        out[nb2 + tid] = s;
    }
}

// ---------------------------------------------------------------------------
extern "C" void kernel_launch(void* const* d_in, const int* in_sizes, int n_in,
                              void* d_out, int out_size)
{
    const float* x      = (const float*)d_in[0];
    const float* z      = (const float*)d_in[1];
    const float* inps   = (const float*)d_in[2];
    const float* preds  = (const float*)d_in[3];
    const float* Wh0    = (const float*)d_in[4];
    const float* bh0    = (const float*)d_in[5];
    const float* Wc0    = (const float*)d_in[6];
    const float* bc0    = (const float*)d_in[7];
    const float* Wih    = (const float*)d_in[8];
    const float* Whh    = (const float*)d_in[9];
    const float* bih    = (const float*)d_in[10];
    const float* bhh    = (const float*)d_in[11];
    const float* Wpi    = (const float*)d_in[12];
    const float* bpi    = (const float*)d_in[13];
    const float* Wmu    = (const float*)d_in[14];
    const float* bmu    = (const float*)d_in[15];
    const float* Wls    = (const float*)d_in[16];
    const float* bls    = (const float*)d_in[17];
    const float* Wcorr  = (const float*)d_in[18];
    const float* bcorr  = (const float*)d_in[19];
    float* out = (float*)d_out;

    cudaFuncSetAttribute(phase2_kernel,
                         cudaFuncAttributeMaxDynamicSharedMemorySize, SMEM2);
    cudaFuncSetAttribute(phase3_kernel,
                         cudaFuncAttributeMaxDynamicSharedMemorySize, SMEM3);

    dim3 g1(NSEQ / 64, 384 / 64);
    phase1_kernel<<<g1, 256>>>(x, z, Wih, Wh0, Wc0, bih, bhh, bh0, bc0);

    phase2_kernel<<<NSEQ / SEQB, 256, SMEM2>>>(inps, preds, Whh, Wih);

    phase3_kernel<<<NSEQ / 2, 256, SMEM3>>>(
        preds, Wpi, bpi, Wmu, bmu, Wls, bls, Wcorr, bcorr, out);
}

// round 13
// speedup vs baseline: 1.7712x; 1.7712x over previous
#include <cuda_runtime.h>
#include <cuda_bf16.h>
#include <math.h>
#include <stdint.h>

#define BSZ 256        // batch B
#define NSEQ 4096      // K*B
#define H 64
#define G4 256
#define ZXD 320
#define LSTM_IN 322
#define TT 50

__device__ __forceinline__ float tanhg(float x) {
    float y;
    asm("tanh.approx.f32 %0, %1;" : "=f"(y) : "f"(x));
    return y;
}
__device__ __forceinline__ float sigg(float x) {
    return fmaf(0.5f, tanhg(0.5f * x), 0.5f);
}
__device__ __forceinline__ uint32_t f2tf(float x) {
    uint32_t r;
    asm("cvt.rna.tf32.f32 %0, %1;" : "=r"(r) : "f"(x));
    return r;
}
__device__ __forceinline__ uint32_t packbf2(float a, float b) {
    __nv_bfloat16 ha = __float2bfloat16(a), hb = __float2bfloat16(b);
    return (uint32_t)__bfloat16_as_ushort(ha)
         | ((uint32_t)__bfloat16_as_ushort(hb) << 16);
}

// m16n8k8 tf32 mma, D += A*B
__device__ __forceinline__ void mma8(float* d, const uint4& a,
                                     uint32_t b0, uint32_t b1) {
    asm volatile(
        "mma.sync.aligned.m16n8k8.row.col.f32.tf32.tf32.f32 "
        "{%0,%1,%2,%3}, {%4,%5,%6,%7}, {%8,%9}, {%0,%1,%2,%3};"
        : "+f"(d[0]), "+f"(d[1]), "+f"(d[2]), "+f"(d[3])
        : "r"(a.x), "r"(a.y), "r"(a.z), "r"(a.w), "r"(b0), "r"(b1));
}
// m16n8k16 bf16 mma, D += A*B
__device__ __forceinline__ void mma16(float* d, const uint4& a,
                                      uint32_t b0, uint32_t b1) {
    asm volatile(
        "mma.sync.aligned.m16n8k16.row.col.f32.bf16.bf16.f32 "
        "{%0,%1,%2,%3}, {%4,%5,%6,%7}, {%8,%9}, {%0,%1,%2,%3};"
        : "+f"(d[0]), "+f"(d[1]), "+f"(d[2]), "+f"(d[3])
        : "r"(a.x), "r"(a.y), "r"(a.z), "r"(a.w), "r"(b0), "r"(b1));
}

// scratch
__device__ float g_G0[NSEQ * G4];   // [n][u*4 + q]
__device__ float g_h0[NSEQ * H];
__device__ float g_c0[NSEQ * H];

// ---------------------------------------------------------------------------
// Phase 1 (unchanged):  [G0 | h0 | c0] = zx @ [Wih[:, :320] | Wh0 | Wc0]^T
// ---------------------------------------------------------------------------
__global__ __launch_bounds__(256) void phase1_kernel(
    const float* __restrict__ x, const float* __restrict__ z,
    const float* __restrict__ Wih, const float* __restrict__ Wh0,
    const float* __restrict__ Wc0,
    const float* __restrict__ bih, const float* __restrict__ bhh,
    const float* __restrict__ bh0, const float* __restrict__ bc0)
{
    __shared__ float As[16][68];
    __shared__ float Ws[16][68];
    const int tid = threadIdx.x;
    const int n0 = blockIdx.x * 64;
    const int c0 = blockIdx.y * 64;
    const int tx = tid & 15, ty = tid >> 4;
    float acc[4][4] = {};

    for (int kt = 0; kt < ZXD; kt += 16) {
        #pragma unroll
        for (int i = 0; i < 4; i++) {
            int e = tid + i * 256;
            int kk = e & 15, rr = e >> 4;
            int n = n0 + rr, m = kt + kk;
            float v = (m < H) ? z[n * H + m]
                              : x[(n & (BSZ - 1)) * 256 + (m - H)];
            As[kk][rr] = v;
        }
        #pragma unroll
        for (int i = 0; i < 4; i++) {
            int e = tid + i * 256;
            int kk = e & 15, cc = e >> 4;
            int j = c0 + cc, m = kt + kk;
            float v;
            if (j < G4)          v = Wih[j * LSTM_IN + m];
            else if (j < G4 + H) v = Wh0[(j - G4) * ZXD + m];
            else                 v = Wc0[(j - G4 - H) * ZXD + m];
            Ws[kk][cc] = v;
        }
        __syncthreads();
        #pragma unroll
        for (int kk = 0; kk < 16; kk++) {
            float a[4], b[4];
            #pragma unroll
            for (int i = 0; i < 4; i++) a[i] = As[kk][ty * 4 + i];
            #pragma unroll
            for (int j = 0; j < 4; j++) b[j] = Ws[kk][tx * 4 + j];
            #pragma unroll
            for (int i = 0; i < 4; i++)
                #pragma unroll
                for (int j = 0; j < 4; j++)
                    acc[i][j] += a[i] * b[j];
        }
        __syncthreads();
    }

    #pragma unroll
    for (int i = 0; i < 4; i++) {
        int n = n0 + ty * 4 + i;
        #pragma unroll
        for (int j = 0; j < 4; j++) {
            int col = c0 + tx * 4 + j;
            float v = acc[i][j];
            if (col < G4) {
                int u = col & 63, q = col >> 6;
                g_G0[n * G4 + u * 4 + q] = v + bih[col] + bhh[col];
            }
            else if (col < G4 + H) g_h0[n * H + (col - G4)]     = v + bh0[col - G4];
            else                   g_c0[n * H + (col - G4 - H)] = v + bc0[col - G4 - H];
        }
    }
}

// ---------------------------------------------------------------------------
// Phase 2: R10 structure, gates on bf16 m16n8k16 (hi/lo 3-term).
// 128 blocks x 32 seqs x 256 threads.
// A_bf [32 x 80] bf16 hi/lo (gates; d at k=64/65);
// A_tf [32 x 72] tf32 hi (heads; const-1 at k=66).
// B gates [256 x 80] bf16 hi/lo packed uint4 [bh0,bh1,bl0,bl1], permuted cols;
// B heads [96 x 72] single tf32 (bias at k=66).
// ---------------------------------------------------------------------------
#define SM_BG   0                       // 32nt*5kt*32*4 = 20480 w
#define SM_BHD  20480                   // 12nt*9kt*32*2 = 6912 w
#define SM_ABH  27392                   // 5kt*2mt*32*4 = 1280 w
#define SM_ABL  28672                   // 1280 w
#define SM_AT   29952                   // 9kt*2mt*32*4 = 2304 w
#define SM_PO   32256                   // 32*100 = 3200 w
#define SM_DT   35456                   // 64 w
#define SM_TOT  35520
#define SMEM_BYTES (SM_TOT * 4)
#define NTH 256

__global__ __launch_bounds__(NTH, 1) void phase2_kernel(
    const float* __restrict__ inp_seqs, const float* __restrict__ pred_seqs,
    const float* __restrict__ Whh, const float* __restrict__ Wih,
    const float* __restrict__ Wpi, const float* __restrict__ bpi,
    const float* __restrict__ Wmu, const float* __restrict__ bmu,
    const float* __restrict__ Wls, const float* __restrict__ bls,
    const float* __restrict__ Wcorr, const float* __restrict__ bcorr,
    float* __restrict__ out)
{
    extern __shared__ float sm[];
    uint32_t* smu = (uint32_t*)sm;
    const int tid  = threadIdx.x;
    const int lane = tid & 31;
    const int warp = tid >> 5;        // 0..7
    const int nb   = blockIdx.x * 32;
    const int m4   = lane & 3;
    const int sr   = lane >> 2;

    // ---- zero A regions ----
    for (int e = tid; e < 1280 * 2 + 2304; e += NTH) sm[SM_ABH + e] = 0.f;

    // ---- stage B gates: bf16 hi/lo, fragment-major, permuted cols ----
    for (int e = tid; e < 256 * 80; e += NTH) {
        int j = e / 80, k = e - (e / 80) * 80;
        int w = j >> 5, i = (j >> 3) & 3, m = (j >> 1) & 3, b = j & 1;
        int u = 8 * w + 2 * m + (i >> 1);
        int q = 2 * (i & 1) + b;
        int row = q * 64 + u;
        float v = 0.f;
        if (k < 64)       v = Whh[row * 64 + k];
        else if (k == 64) v = Wih[row * LSTM_IN + 320];
        else if (k == 65) v = Wih[row * LSTM_IN + 321];
        __nv_bfloat16 hb = __float2bfloat16(v);
        __nv_bfloat16 lb = __float2bfloat16(v - __bfloat162float(hb));
        int nt = j >> 3, kt = k >> 4, kk = k & 15;
        int lanep = (j & 7) * 4 + ((kk >> 1) & 3);
        int breg = kk >> 3, half = kk & 1;
        char* p = (char*)(smu + SM_BG)
                  + (((nt * 5 + kt) * 32 + lanep) * 4 + breg) * 4 + half * 2;
        *(__nv_bfloat16*)p       = hb;
        *(__nv_bfloat16*)(p + 8) = lb;
    }
    // ---- stage B heads (single tf32, bias at k=66) ----
    for (int e = tid; e < 96 * 72; e += NTH) {
        int jj = e / 72, k = e - (e / 72) * 72;
        float v = 0.f;
        if (k < 64) {
            if (jj < 16)      v = Wpi[jj * 64 + k];
            else if (jj < 48) v = Wmu[(jj - 16) * 64 + k];
            else if (jj < 80) v = Wls[(jj - 48) * 64 + k];
            else              v = Wcorr[(jj - 80) * 64 + k];
        } else if (k == 66) {
            if (jj < 16)      v = bpi[jj];
            else if (jj < 48) v = bmu[jj - 16];
            else if (jj < 80) v = bls[jj - 48];
            else              v = bcorr[jj - 80];
        }
        int nt = jj >> 3, kt = k >> 3, kl = k & 7;
        int lanep = (jj & 7) * 4 + (kl & 3);
        int r = kl >> 2;
        smu[SM_BHD + ((nt * 9 + kt) * 32 + lanep) * 2 + r] = f2tf(v);
    }
    __syncthreads();   // zeros done before partial A fills

    // ---- stage A: h0 -> bf16 (hi+lo) and tf32 (hi) ----
    for (int e = tid; e < 32 * 64; e += NTH) {
        int s = e >> 6, k = e & 63;
        float v = g_h0[(nb + s) * 64 + k];
        // bf16
        {
            __nv_bfloat16 hb = __float2bfloat16(v);
            __nv_bfloat16 lb = __float2bfloat16(v - __bfloat162float(hb));
            int mt = s >> 4, rr = s & 15, kt = k >> 4, kk = k & 15;
            int lanew = (rr & 7) * 4 + ((kk >> 1) & 3);
            int reg = (rr >> 3) + 2 * (kk >> 3);
            int half = kk & 1;
            int byteoff = (((kt * 2 + mt) * 32 + lanew) * 4 + reg) * 4 + half * 2;
            *(__nv_bfloat16*)((char*)(smu + SM_ABH) + byteoff) = hb;
            *(__nv_bfloat16*)((char*)(smu + SM_ABL) + byteoff) = lb;
        }
        // tf32
        {
            int mt = s >> 4, kt = k >> 3;
            int lanep = (s & 7) * 4 + (k & 3);
            int r = ((s >> 3) & 1) + 2 * ((k >> 2) & 1);
            smu[SM_AT + ((kt * 2 + mt) * 32 + lanep) * 4 + r] = f2tf(v);
        }
    }
    // ---- stage A: d0 (bf16) + const-1 (tf32, k=66) ----
    if (tid < 32) {
        int s = tid;
        int b = (nb + s) & (BSZ - 1);
        float dx = inp_seqs[(b * 8 + 7) * 24 + 20];
        float dy = inp_seqs[(b * 8 + 7) * 24 + 21];
        int mt = s >> 4, rr = s & 15;
        int idx = (((4 * 2 + mt) * 32 + (rr & 7) * 4) * 4 + (rr >> 3));
        __nv_bfloat16 hx = __float2bfloat16(dx), hy = __float2bfloat16(dy);
        float rx = dx - __bfloat162float(hx), ry = dy - __bfloat162float(hy);
        smu[SM_ABH + idx] = packbf2(dx, dy);
        smu[SM_ABL + idx] = packbf2(rx, ry);
        // tf32 const-1 at k=66
        int lanep = (s & 7) * 4 + (66 & 3);
        int r = ((s >> 3) & 1) + 2 * ((66 >> 2) & 1);
        smu[SM_AT + (((66 >> 3) * 2 + mt) * 32 + lanep) * 4 + r] = f2tf(1.0f);
    }

    // ---- register state: G0 + c for 4 seqs x 2 units ----
    float G0r[4][2][4];
    float c[4][2];
    #pragma unroll
    for (int j = 0; j < 4; j++) {
        int s = sr + (j & 1) * 8 + (j >> 1) * 16;
        int n = nb + s;
        #pragma unroll
        for (int dl = 0; dl < 2; dl++) {
            int u = 8 * warp + 2 * m4 + dl;
            float4 g0 = *(const float4*)(g_G0 + n * 256 + u * 4);
            G0r[j][dl][0] = g0.x; G0r[j][dl][1] = g0.y;
            G0r[j][dl][2] = g0.z; G0r[j][dl][3] = g0.w;
            c[j][dl] = g_c0[n * 64 + u];
        }
    }

    const int b_mine = (nb + lane) & (BSZ - 1);
    const int sh = lane >> 4;
    const int gc = lane & 15;
    float lacc[2] = {0.f, 0.f};

    const uint4* abh = (const uint4*)(smu + SM_ABH) + lane;
    const uint4* abl = (const uint4*)(smu + SM_ABL) + lane;
    const uint4* atp = (const uint4*)(smu + SM_AT) + lane;
    const uint4* bgp = (const uint4*)(smu + SM_BG) + (4 * warp * 5) * 32 + lane;
    const uint2* bhp = (const uint2*)(smu + SM_BHD) + (2 * warp * 9) * 32 + lane;

    // per-thread h-write constants (bf16 A)
    const int u0 = 8 * warp + 2 * m4;
    const int kt2 = u0 >> 4;
    const int lane_w = ((u0 & 15) >> 1) & 3;
    const int reg_b = 2 * ((u0 & 15) >> 3);

    __syncthreads();

    for (int t = 1; t <= TT; t++) {
        // prefetch pred row t-1 (decode for t+1 AND GMM target for t)
        float pdx = 0.f, pdy = 0.f;
        if (tid < 32) {
            const float* pr = pred_seqs + (b_mine * TT + (t - 1)) * 24 + 20;
            pdx = pr[0];
            pdy = pr[1];
        }

        // ======== gates MMA: bf16 3-term (120 mma16) ========
        float acc[4][2][4];
        #pragma unroll
        for (int a = 0; a < 4; a++)
            #pragma unroll
            for (int b = 0; b < 2; b++)
                #pragma unroll
                for (int r = 0; r < 4; r++) acc[a][b][r] = 0.f;

        #pragma unroll
        for (int kt = 0; kt < 5; kt++) {
            uint4 ah0 = abh[(kt * 2 + 0) * 32];
            uint4 ah1 = abh[(kt * 2 + 1) * 32];
            uint4 al0 = abl[(kt * 2 + 0) * 32];
            uint4 al1 = abl[(kt * 2 + 1) * 32];
            #pragma unroll
            for (int ntl = 0; ntl < 4; ntl++) {
                uint4 B = bgp[(ntl * 5 + kt) * 32];
                mma16(acc[ntl][0], ah0, B.x, B.y);
                mma16(acc[ntl][1], ah1, B.x, B.y);
                mma16(acc[ntl][0], al0, B.x, B.y);
                mma16(acc[ntl][1], al1, B.x, B.y);
                mma16(acc[ntl][0], ah0, B.z, B.w);
                mma16(acc[ntl][1], ah1, B.z, B.w);
            }
        }

        // ======== pointwise LSTM (registers) ========
        float hreg[4][2];
        #pragma unroll
        for (int j = 0; j < 4; j++) {
            int mt = j >> 1, rh = j & 1;
            #pragma unroll
            for (int dl = 0; dl < 2; dl++) {
                float gi = acc[2 * dl][mt][2 * rh + 0] + G0r[j][dl][0];
                float gf = acc[2 * dl][mt][2 * rh + 1] + G0r[j][dl][1];
                float gg = acc[2 * dl + 1][mt][2 * rh + 0] + G0r[j][dl][2];
                float go = acc[2 * dl + 1][mt][2 * rh + 1] + G0r[j][dl][3];
                float cc = sigg(gf) * c[j][dl] + sigg(gi) * tanhg(gg);
                c[j][dl] = cc;
                hreg[j][dl] = sigg(go) * tanhg(cc);
            }
        }
        __syncthreads();   // all A reads done

        // ======== write h (bf16 hi/lo + tf32) + d(t+1) + DT ========
        #pragma unroll
        for (int j = 0; j < 4; j++) {
            int mt = j >> 1;
            int s = sr + (j & 1) * 8 + mt * 16;
            int rr = s & 15;
            float h0v = hreg[j][0], h1v = hreg[j][1];
            // bf16 pair (units u0, u0+1 are k-adjacent -> one word each)
            {
                __nv_bfloat16 b0 = __float2bfloat16(h0v);
                __nv_bfloat16 b1 = __float2bfloat16(h1v);
                float r0 = h0v - __bfloat162float(b0);
                float r1 = h1v - __bfloat162float(b1);
                int idx = (((kt2 * 2 + mt) * 32 + (rr & 7) * 4 + lane_w) * 4)
                          + (rr >> 3) + reg_b;
                smu[SM_ABH + idx] = (uint32_t)__bfloat16_as_ushort(b0)
                                  | ((uint32_t)__bfloat16_as_ushort(b1) << 16);
                smu[SM_ABL + idx] = packbf2(r0, r1);
            }
            // tf32
            #pragma unroll
            for (int dl = 0; dl < 2; dl++) {
                int u = u0 + dl;
                int kt = u >> 3;
                int lanep = (s & 7) * 4 + (u & 3);
                int r = ((s >> 3) & 1) + 2 * ((u >> 2) & 1);
                smu[SM_AT + ((kt * 2 + mt) * 32 + lanep) * 4 + r] =
                    f2tf(dl ? h1v : h0v);
            }
        }
        if (tid < 32) {
            int s = lane;
            sm[SM_DT + s * 2]     = pdx;
            sm[SM_DT + s * 2 + 1] = pdy;
            int mt = s >> 4, rr = s & 15;
            int idx = (((4 * 2 + mt) * 32 + (rr & 7) * 4) * 4 + (rr >> 3));
            float rx, ry;
            {
                __nv_bfloat16 hx = __float2bfloat16(pdx);
                __nv_bfloat16 hy = __float2bfloat16(pdy);
                rx = pdx - __bfloat162float(hx);
                ry = pdy - __bfloat162float(hy);
            }
            smu[SM_ABH + idx] = packbf2(pdx, pdy);
            smu[SM_ABL + idx] = packbf2(rx, ry);
        }
        __syncthreads();   // new A + DT visible

        // ======== heads MMA (warps 0-5, tf32 single) ========
        if (warp < 6) {
            float facc[2][2][4];
            #pragma unroll
            for (int a = 0; a < 2; a++)
                #pragma unroll
                for (int b = 0; b < 2; b++)
                    #pragma unroll
                    for (int r = 0; r < 4; r++) facc[a][b][r] = 0.f;
            #pragma unroll
            for (int kt = 0; kt < 9; kt++) {
                uint4 ah0 = atp[(kt * 2 + 0) * 32];
                uint4 ah1 = atp[(kt * 2 + 1) * 32];
                uint2 Bh0 = bhp[(0 * 9 + kt) * 32];
                uint2 Bh1 = bhp[(1 * 9 + kt) * 32];
                mma8(facc[0][0], ah0, Bh0.x, Bh0.y);
                mma8(facc[0][1], ah1, Bh0.x, Bh0.y);
                mma8(facc[1][0], ah0, Bh1.x, Bh1.y);
                mma8(facc[1][1], ah1, Bh1.x, Bh1.y);
            }
            #pragma unroll
            for (int ntl = 0; ntl < 2; ntl++) {
                int jc = 16 * warp + 8 * ntl + 2 * m4;
                #pragma unroll
                for (int mt = 0; mt < 2; mt++) {
                    int r0 = sr + 16 * mt;
                    *(float2*)(sm + SM_PO + r0 * 100 + jc) =
                        make_float2(facc[ntl][mt][0], facc[ntl][mt][1]);
                    *(float2*)(sm + SM_PO + (r0 + 8) * 100 + jc) =
                        make_float2(facc[ntl][mt][2], facc[ntl][mt][3]);
                }
            }
        }
        __syncthreads();   // Po visible

        // ======== GMM + LSE: warp = 4 seqs (2 passes x 2 seqs x 16 comps) ====
        #pragma unroll
        for (int it = 0; it < 2; it++) {
            int gs = 4 * warp + 2 * it + sh;
            float txv = sm[SM_DT + gs * 2];
            float tyv = sm[SM_DT + gs * 2 + 1];
            const float* pr = sm + SM_PO + gs * 100;
            float pi  = pr[gc];
            float2 mu  = *(const float2*)(pr + 16 + 2 * gc);
            float2 lsv = *(const float2*)(pr + 48 + 2 * gc);
            float corr = tanhg(pr[80 + gc]);
            float ls0 = fminf(fmaxf(lsv.x, -10.f), 10.f);
            float ls1 = fminf(fmaxf(lsv.y, -10.f), 10.f);
            float dx = txv - mu.x, dy = tyv - mu.y;
            float z0 = dx * __expf(-ls0);
            float z1 = dy * __expf(-ls1);
            float omr  = 1.f - corr * corr;
            float quad = z0 * z0 + z1 * z1 - 2.f * corr * z0 * z1;
            float cv = -1.8378770664093453f - (ls0 + ls1)
                       - 0.5f * __logf(omr) - 0.5f * __fdividef(quad, omr);
            float a = pi + cv;
            float b2 = pi;
            float ma = a, mb = b2;
            #pragma unroll
            for (int xm = 1; xm < 16; xm <<= 1) {
                ma = fmaxf(ma, __shfl_xor_sync(0xFFFFFFFFu, ma, xm));
                mb = fmaxf(mb, __shfl_xor_sync(0xFFFFFFFFu, mb, xm));
            }
            float ea = __expf(a - ma);
            float eb = __expf(b2 - mb);
            #pragma unroll
            for (int xm = 1; xm < 16; xm <<= 1) {
                ea += __shfl_xor_sync(0xFFFFFFFFu, ea, xm);
                eb += __shfl_xor_sync(0xFFFFFFFFu, eb, xm);
            }
            float lp = (ma + __logf(ea)) - (mb + __logf(eb));
            lacc[it] += fminf(lp, 50.f);
        }
        // no trailing barrier: DT/Po rewritten only after next step's barriers
    }

    if ((lane & 15) == 0) {
        out[nb + 4 * warp + 0 + sh] = lacc[0];
        out[nb + 4 * warp + 2 + sh] = lacc[1];
    }
}

// ---------------------------------------------------------------------------
extern "C" void kernel_launch(void* const* d_in, const int* in_sizes, int n_in,
                              void* d_out, int out_size)
{
    const float* x      = (const float*)d_in[0];
    const float* z      = (const float*)d_in[1];
    const float* inps   = (const float*)d_in[2];
    const float* preds  = (const float*)d_in[3];
    const float* Wh0    = (const float*)d_in[4];
    const float* bh0    = (const float*)d_in[5];
    const float* Wc0    = (const float*)d_in[6];
    const float* bc0    = (const float*)d_in[7];
    const float* Wih    = (const float*)d_in[8];
    const float* Whh    = (const float*)d_in[9];
    const float* bih    = (const float*)d_in[10];
    const float* bhh    = (const float*)d_in[11];
    const float* Wpi    = (const float*)d_in[12];
    const float* bpi    = (const float*)d_in[13];
    const float* Wmu    = (const float*)d_in[14];
    const float* bmu    = (const float*)d_in[15];
    const float* Wls    = (const float*)d_in[16];
    const float* bls    = (const float*)d_in[17];
    const float* Wcorr  = (const float*)d_in[18];
    const float* bcorr  = (const float*)d_in[19];
    float* out = (float*)d_out;

    cudaFuncSetAttribute(phase2_kernel,
                         cudaFuncAttributeMaxDynamicSharedMemorySize, SMEM_BYTES);

    dim3 g1(NSEQ / 64, 384 / 64);
    phase1_kernel<<<g1, 256>>>(x, z, Wih, Wh0, Wc0, bih, bhh, bh0, bc0);

    phase2_kernel<<<NSEQ / 32, NTH, SMEM_BYTES>>>(
        inps, preds, Whh, Wih,
        Wpi, bpi, Wmu, bmu, Wls, bls, Wcorr, bcorr, out);
}